// round 1
// baseline (speedup 1.0000x reference)
#include <cuda_runtime.h>

#define C_CH 32
#define HW   256
#define KS2  9
#define OCH  288   // C*KS2
#define QS   32    // coarse spatial size after pool
#define NB   4

// Scratch (no allocations allowed in kernel_launch)
__device__ float g_p[NB * C_CH * QS * QS];   // [n][c][32][32] pooled coarse features
__device__ float g_y[NB * OCH * QS * QS];    // [n][o][32][32] coarse per-pixel filters

// ---------------------------------------------------------------------------
// Kernel A: psf [4,32,256,256] -> bilinear 1/4 (exact: weights all 0.25,
// src = 4u+1.5 so samples are avg of a fixed 2x2) -> maxpool2 -> p [4,32,32,32]
// ---------------------------------------------------------------------------
__global__ void kA(const float* __restrict__ psf) {
    int t = blockIdx.x * blockDim.x + threadIdx.x;   // 4*32*32*32 = 131072
    int j = t & 31;
    int i = (t >> 5) & 31;
    int c = (t >> 10) & 31;
    int n = t >> 15;
    const float* base = psf + ((size_t)(n * C_CH + c) * HW) * HW;
    float m = -3.4e38f;
#pragma unroll
    for (int uu = 0; uu < 2; uu++) {
        int r0 = 4 * (2 * i + uu) + 1;               // rows r0, r0+1 (never OOB)
#pragma unroll
        for (int vv = 0; vv < 2; vv++) {
            int c0 = 4 * (2 * j + vv) + 1;           // cols c0, c0+1 (never OOB)
            const float* p0 = base + r0 * HW + c0;
            float s = 0.25f * (p0[0] + p0[1] + p0[HW] + p0[HW + 1]);
            m = fmaxf(m, s);
        }
    }
    g_p[t] = m;
}

// ---------------------------------------------------------------------------
// Kernel B: y = lrelu(p @ w1^T + b1) + (p @ ws^T + bs)   -> [4,288,32,32]
// einsum('nchw,oc->nohw'): y[n,o,pix] = sum_c p[n,c,pix] * W[o,c]
// ---------------------------------------------------------------------------
__global__ void kB(const float* __restrict__ w1, const float* __restrict__ b1,
                   const float* __restrict__ ws, const float* __restrict__ bs) {
    int t = blockIdx.x * blockDim.x + threadIdx.x;   // 4*288*1024
    int pix = t & 1023;
    int o = (t >> 10) % OCH;
    int n = t / (1024 * OCH);
    const float* pbase = g_p + (size_t)(n * C_CH) * (QS * QS) + pix;
    float a1 = 0.f, a2 = 0.f;
#pragma unroll
    for (int c = 0; c < C_CH; c++) {
        float pv = pbase[c * (QS * QS)];
        a1 = fmaf(pv, w1[o * C_CH + c], a1);
        a2 = fmaf(pv, ws[o * C_CH + c], a2);
    }
    a1 += b1[o];
    a2 += bs[o];
    float act = (a1 >= 0.f) ? a1 : 0.2f * a1;
    g_y[t] = act + a2;
}

// ---------------------------------------------------------------------------
// Kernel C: fused x8 bilinear upsample of y + FAC 3x3 dynamic filtering.
// Block: (tile of 16 output rows) x (full 256-wide row) for one (n, c).
// For h = 16*tt + hh:  i0 = (h-4)>>3 ; relative staged row t0 = {0,1,2} is a
// compile-time function of hh; wy = 0.125*hh + 0.5625 - t0 (compile-time).
// Staged coarse rows are clamp(2*tt-1 + r, 0, 31) so all boundary clamping is
// handled by the staging (duplicated rows), matching align_corners=False.
// ---------------------------------------------------------------------------
__global__ void __launch_bounds__(256) kC(const float* __restrict__ fm,
                                          float* __restrict__ out) {
    __shared__ float fmt[18][258];       // fm tile rows h0-1..h0+16, cols -1..256
    __shared__ float yt[9][4][32];       // 9 taps x 4 coarse rows x 32 coarse cols

    const int tt = blockIdx.x;           // 0..15  (16-row tiles)
    const int c  = blockIdx.y;           // 0..31
    const int n  = blockIdx.z;           // 0..3
    const int w  = threadIdx.x;          // 0..255 (one output column per thread)
    const int h0 = tt * 16;
    const int crBase = 2 * tt - 1;

    // ---- stage featuremap tile (zero padded ring) ----
    const float* fbase = fm + ((size_t)(n * C_CH + c) * HW) * HW;
    for (int r = 0; r < 18; r++) {
        int gh = h0 - 1 + r;
        bool rowok = (gh >= 0) && (gh < HW);
        for (int col = w; col < 258; col += 256) {
            int gw = col - 1;
            float v = 0.f;
            if (rowok && gw >= 0 && gw < HW) v = fbase[gh * HW + gw];
            fmt[r][col] = v;
        }
    }

    // ---- stage coarse filter tile (row-clamped) ----
    const float* ybase = g_y + (size_t)(n * OCH + c * KS2) * (QS * QS);
    for (int idx = w; idx < 9 * 4 * 32; idx += 256) {
        int k = idx >> 7;
        int rem = idx & 127;
        int r = rem >> 5;
        int col = rem & 31;
        int cr = crBase + r;
        cr = min(max(cr, 0), QS - 1);
        yt[k][r][col] = ybase[k * (QS * QS) + cr * QS + col];
    }
    __syncthreads();

    // ---- per-thread horizontal lerp of all 4 staged rows x 9 taps ----
    int ix0 = (w - 4) >> 3;                       // arithmetic shift: floors
    float wx = (float)w * 0.125f - 0.4375f - (float)ix0;
    int jx0 = max(ix0, 0);
    int jx1 = min(ix0 + 1, QS - 1);
    float hl[4][9];
#pragma unroll
    for (int r = 0; r < 4; r++) {
#pragma unroll
        for (int k = 0; k < 9; k++) {
            float a = yt[k][r][jx0];
            float b = yt[k][r][jx1];
            hl[r][k] = a + wx * (b - a);
        }
    }

    // ---- rolling 3x3 featuremap window + vertical lerp + accumulate ----
    float win[3][3];
#pragma unroll
    for (int d = 0; d < 3; d++) {
        win[0][d] = fmt[0][w + d];
        win[1][d] = fmt[1][w + d];
    }

    float* obase = out + (((size_t)(n * C_CH + c) * HW + h0) * HW) + w;

#pragma unroll
    for (int hh = 0; hh < 16; hh++) {
#pragma unroll
        for (int d = 0; d < 3; d++) win[2][d] = fmt[hh + 2][w + d];

        const int t0 = (hh < 4) ? 0 : ((hh < 12) ? 1 : 2);
        const float wy = (float)hh * 0.125f + 0.5625f - (float)t0;

        float acc = 0.f;
#pragma unroll
        for (int dy = 0; dy < 3; dy++) {
#pragma unroll
            for (int dx = 0; dx < 3; dx++) {
                int k = dy * 3 + dx;
                float ft = hl[t0][k] + wy * (hl[t0 + 1][k] - hl[t0][k]);
                acc = fmaf(ft, win[dy][dx], acc);
            }
        }
        obase[hh * HW] = acc;

#pragma unroll
        for (int d = 0; d < 3; d++) {
            win[0][d] = win[1][d];
            win[1][d] = win[2][d];
        }
    }
}

// ---------------------------------------------------------------------------
extern "C" void kernel_launch(void* const* d_in, const int* in_sizes, int n_in,
                              void* d_out, int out_size) {
    const float* psf = (const float*)d_in[0];
    const float* fm  = (const float*)d_in[1];
    const float* w1  = (const float*)d_in[2];
    const float* b1  = (const float*)d_in[3];
    const float* ws  = (const float*)d_in[4];
    const float* bs  = (const float*)d_in[5];
    float* out = (float*)d_out;

    kA<<<512, 256>>>(psf);                 // 131072 threads
    kB<<<4608, 256>>>(w1, b1, ws, bs);     // 1,179,648 threads
    dim3 gc(16, C_CH, NB);
    kC<<<gc, 256>>>(fm, out);
}